// round 15
// baseline (speedup 1.0000x reference)
#include <cuda_runtime.h>
#include <cuda_fp16.h>
#include <math.h>
#include <stdint.h>

namespace {
constexpr int Bb = 8;
constexpr int Hh = 4;
constexpr int Nn = 1024;
constexpr int KV = 960;
constexpr int CSUM = 960;   // 64+128+256+512
}

// ---------------------------------------------------------------------------
// Device-global scratch (allocation-free). Per-branch private regions.
// ---------------------------------------------------------------------------
constexpr size_t IN_ARENA = 24842240;
__device__ __half g_inH[IN_ARENA];
__device__ __half g_inL[IN_ARENA];

__device__ __half g_KtH[(size_t)Bb * Hh * KV * Nn];
__device__ __half g_KtL[(size_t)Bb * Hh * KV * Nn];
__device__ __half g_VH [(size_t)Bb * Hh * Nn * KV];
__device__ __half g_VL [(size_t)Bb * Hh * Nn * KV];
__device__ __half g_QtH[(size_t)Bb * Hh * CSUM * Nn];
__device__ __half g_QtL[(size_t)Bb * Hh * CSUM * Nn];
__device__ float  g_S  [(size_t)Bb * Hh * CSUM * KV];
__device__ __half g_PH [(size_t)Bb * Hh * CSUM * KV];
__device__ __half g_PL [(size_t)Bb * Hh * CSUM * KV];
__device__ __half g_cH [(size_t)Bb * Nn * CSUM];
__device__ __half g_cL [(size_t)Bb * Nn * CSUM];
__device__ float  g_stats[4 * Bb * Hh * 2];
__device__ float2 g_part[4 * Bb * Hh * 16];

__device__ __forceinline__ uint32_t smem_u32(const void* p) {
    uint32_t a;
    asm("{ .reg .u64 t; cvta.to.shared.u64 t, %1; cvt.u32.u64 %0, t; }" : "=r"(a) : "l"(p));
    return a;
}

#define LDMX4(r, addr)                                                          \
    asm volatile("ldmatrix.sync.aligned.m8n8.x4.shared.b16 {%0,%1,%2,%3}, [%4];" \
        : "=r"((r)[0]), "=r"((r)[1]), "=r"((r)[2]), "=r"((r)[3]) : "r"(addr))
#define MMA16816(d, a, b)                                                       \
    asm volatile("mma.sync.aligned.m16n8k16.row.col.f32.f16.f16.f32 "           \
        "{%0,%1,%2,%3}, {%4,%5,%6,%7}, {%8,%9}, {%0,%1,%2,%3};"                 \
        : "+f"((d)[0]), "+f"((d)[1]), "+f"((d)[2]), "+f"((d)[3])                \
        : "r"((a)[0]), "r"((a)[1]), "r"((a)[2]), "r"((a)[3]),                   \
          "r"((b)[0]), "r"((b)[1]))
#define CP16(dst, src, vsz)                                                     \
    asm volatile("cp.async.ca.shared.global [%0], [%1], 16, %2;"                \
        :: "r"(dst), "l"(src), "r"(vsz) : "memory")
#define CP_COMMIT asm volatile("cp.async.commit_group;" ::: "memory")
#define CP_WAIT1  asm volatile("cp.async.wait_group 1;" ::: "memory")
#define CP_WAIT0  asm volatile("cp.async.wait_group 0;" ::: "memory")

// split fp32 pair -> fp16 hi pair + fp16 lo (residual) pair
__device__ __forceinline__ void splitf16(float x, float y, uint32_t& h, uint32_t& l) {
    __half2 hh = __floats2half2_rn(x, y);
    const float hx = __low2float(hh);
    const float hy = __high2float(hh);
    __half2 ll = __floats2half2_rn(x - hx, y - hy);
    h = *reinterpret_cast<uint32_t*>(&hh);
    l = *reinterpret_cast<uint32_t*>(&ll);
}

// ---------------------------------------------------------------------------
// Single fused input conversion over the whole arena.
// ---------------------------------------------------------------------------
struct ConvParams {
    const float* src[15];
    long         cum4[16];
};

__global__ void conv_all(ConvParams P, __half* __restrict__ hi,
                         __half* __restrict__ lo, long total4)
{
    const long i = (long)blockIdx.x * blockDim.x + threadIdx.x;
    if (i >= total4) return;
    int j = 0;
#pragma unroll
    for (int k = 1; k < 15; ++k) if (i >= P.cum4[k]) j = k;
    const float4 v = reinterpret_cast<const float4*>(P.src[j])[i - P.cum4[j]];
    uint32_t h01, l01, h23, l23;
    splitf16(v.x, v.y, h01, l01);
    splitf16(v.z, v.w, h23, l23);
    reinterpret_cast<uint2*>(hi)[i] = make_uint2(h01, h23);
    reinterpret_cast<uint2*>(lo)[i] = make_uint2(l01, l23);
}

// ---------------------------------------------------------------------------
// NT GEMM: fp16 split, 2-product (A-hi x B-hi + A-hi x B-lo). A-lo never read.
// 3-stage cp.async pipeline for NT<=192 (single sync, issue overlapped);
// 2-stage fallback only for NT=256.
// ---------------------------------------------------------------------------
template<int NT, bool SPLIT_OUT>
__global__ __launch_bounds__(256)
void gemm_hf(const __half* __restrict__ AH,
             const __half* __restrict__ BH, const __half* __restrict__ BL,
             float* __restrict__ Cf,
             __half* __restrict__ CH, __half* __restrict__ CL,
             int M, int N, int K,
             long sAo, long sAi, long sBo, long sBi, long sC,
             int hDiv, int nAcc, long accA, long accB, float scale)
{
    constexpr int NN    = NT / 32;
    constexpr int BPU   = NT * 8;
    constexpr int UNITS = 1024 + 2 * BPU;
    constexpr int NU    = UNITS / 256;
    constexpr int STAGE = 16384 + 2 * NT * 128;
    constexpr int NST   = (NT >= 256) ? 2 : 3;

    extern __shared__ __align__(128) char smdyn[];
    const uint32_t su = smem_u32(smdyn);

    const int tid  = threadIdx.x;
    const int lane = tid & 31;
    const int wid  = tid >> 5;
    const int wm   = (wid >> 2) * 64;
    const int wn   = (wid & 3) * (NT / 4);

    const int m0 = blockIdx.y * 128;
    const int n0 = blockIdx.x * NT;
    const int z  = blockIdx.z;

    const long aOff = (long)(z / hDiv) * sAo + (long)(z % hDiv) * sAi;
    const long bOff = (long)(z / hDiv) * sBo + (long)(z % hDiv) * sBi;
    const __half* AHb = AH + aOff;
    const __half* BHb = BH + bOff;
    const __half* BLb = BL + bOff;
    const int mRem = M - m0;

    const int aRow  = (lane & 7) + ((lane >> 3) & 1) * 8;
    const int aSlab = (lane >> 4) * 16;

    float acc[4][NN][4];
#pragma unroll
    for (int i = 0; i < 4; i++)
#pragma unroll
        for (int j = 0; j < NN; j++)
#pragma unroll
            for (int r = 0; r < 4; r++) acc[i][j][r] = 0.f;

    const int kChunks = K >> 6;
    const int nChunks = nAcc * kChunks;

    auto issue = [&](int c) {
        const int hn = c / kChunks;
        const int k0 = (c % kChunks) << 6;
        const __half* pa  = AHb + (long)hn * accA;
        const __half* pb[2] = { BHb + (long)hn * accB, BLb + (long)hn * accB };
        const uint32_t buf = su + (uint32_t)(c % NST) * STAGE;
#pragma unroll
        for (int j = 0; j < NU; ++j) {
            const int u = tid + j * 256;
            const __half* src;
            uint32_t dst;
            int vsz;
            if (u < 1024) {
                const int row = u >> 3, g = u & 7;
                const int rr = (row < mRem) ? row : 0;
                vsz = (row < mRem) ? 16 : 0;
                src = pa + (long)(m0 + rr) * K + k0 + g * 8;
                dst = buf + (uint32_t)row * 128u + (uint32_t)((g ^ (row & 7)) << 4);
            } else {
                const int ub = u - 1024;
                const int pl = ub / BPU, w = ub % BPU;
                const int row = w >> 3, g = w & 7;
                const int rr = (n0 + row < N) ? row : 0;
                vsz = (n0 + row < N) ? 16 : 0;
                src = pb[pl] + (long)(n0 + rr) * K + k0 + g * 8;
                dst = buf + 16384u + (uint32_t)pl * (uint32_t)(NT * 128)
                          + (uint32_t)row * 128u + (uint32_t)((g ^ (row & 7)) << 4);
            }
            CP16(dst, src, vsz);
        }
    };

    issue(0); CP_COMMIT;
    if (nChunks > 1) { issue(1); CP_COMMIT; }

    for (int c = 0; c < nChunks; ++c) {
        if (c + 1 < nChunks) { CP_WAIT1; } else { CP_WAIT0; }
        __syncthreads();
        if (NST == 3 && c + 2 < nChunks) { issue(c + 2); CP_COMMIT; }

        const uint32_t buf = su + (uint32_t)(c % NST) * STAGE;
        const uint32_t aHi = buf;
        const uint32_t bHi = buf + 16384;
        const uint32_t bLo = buf + 16384 + NT * 128;

#pragma unroll
        for (int ks = 0; ks < 4; ++ks) {
            const int cbase = ks * 32;
            uint32_t ah[4][4];
#pragma unroll
            for (int mt = 0; mt < 4; ++mt) {
                const int row = wm + mt * 16 + aRow;
                const int cb  = cbase + aSlab;
                const uint32_t off = (uint32_t)row * 128u
                                   + (uint32_t)((((cb >> 4) ^ (row & 7))) << 4);
                LDMX4(ah[mt], aHi + off);
            }
            uint32_t bh[NN][2], bl[NN][2];
#pragma unroll
            for (int p = 0; p < NN / 2; ++p) {
                const int mr  = lane >> 3;
                const int row = wn + p * 16 + (mr >> 1) * 8 + (lane & 7);
                const int cb  = cbase + (mr & 1) * 16;
                const uint32_t off = (uint32_t)row * 128u
                                   + (uint32_t)((((cb >> 4) ^ (row & 7))) << 4);
                uint32_t q[4];
                LDMX4(q, bHi + off);
                bh[2*p][0] = q[0]; bh[2*p][1] = q[1];
                bh[2*p+1][0] = q[2]; bh[2*p+1][1] = q[3];
                LDMX4(q, bLo + off);
                bl[2*p][0] = q[0]; bl[2*p][1] = q[1];
                bl[2*p+1][0] = q[2]; bl[2*p+1][1] = q[3];
            }
#pragma unroll
            for (int mt = 0; mt < 4; ++mt)
#pragma unroll
                for (int nt = 0; nt < NN; ++nt) {
                    MMA16816(acc[mt][nt], ah[mt], bh[nt]);
                    MMA16816(acc[mt][nt], ah[mt], bl[nt]);
                }
        }

        if (NST == 2) {
            __syncthreads();
            if (c + 2 < nChunks) { issue(c + 2); CP_COMMIT; }
        }
    }

    // ---- epilogue ----
    float* Cfp = SPLIT_OUT ? nullptr : (Cf + (long)z * sC);
    __half* CHp = SPLIT_OUT ? (CH + (long)z * sC) : nullptr;
    __half* CLp = SPLIT_OUT ? (CL + (long)z * sC) : nullptr;

#pragma unroll
    for (int mt = 0; mt < 4; ++mt) {
#pragma unroll
        for (int nt = 0; nt < NN; ++nt) {
            const int m1 = m0 + wm + mt * 16 + (lane >> 2);
            const int n  = n0 + wn + nt * 8 + (lane & 3) * 2;
            if (n >= N) continue;
#pragma unroll
            for (int half = 0; half < 2; ++half) {
                const int m = m1 + half * 8;
                if (m >= M) continue;
                const float x = acc[mt][nt][half * 2 + 0] * scale;
                const float y = acc[mt][nt][half * 2 + 1] * scale;
                if (SPLIT_OUT) {
                    uint32_t h, l;
                    splitf16(x, y, h, l);
                    *reinterpret_cast<uint32_t*>(CHp + (long)m * N + n) = h;
                    *reinterpret_cast<uint32_t*>(CLp + (long)m * N + n) = l;
                } else {
                    *reinterpret_cast<float2*>(Cfp + (long)m * N + n) = make_float2(x, y);
                }
            }
        }
    }
}

// ---------------------------------------------------------------------------
// Two-phase instance-norm stats + softmax (emits split probs)
// ---------------------------------------------------------------------------
__inline__ __device__ float warpSum(float v) {
#pragma unroll
    for (int o = 16; o; o >>= 1) v += __shfl_xor_sync(0xffffffffu, v, o);
    return v;
}
__inline__ __device__ float warpMax(float v) {
#pragma unroll
    for (int o = 16; o; o >>= 1) v = fmaxf(v, __shfl_xor_sync(0xffffffffu, v, o));
    return v;
}

__global__ void stats_p1(const float* __restrict__ S, float2* __restrict__ part, int C)
{
    const int z = blockIdx.x, p = blockIdx.y;
    const long n = (long)C * KV;
    const long len = (n + 15) >> 4;
    const long lo = (long)p * len;
    const long hi = (lo + len < n) ? lo + len : n;
    const float* base = S + (long)z * n;
    float s = 0.f, sq = 0.f;
    for (long i = lo + threadIdx.x; i < hi; i += blockDim.x) {
        const float x = base[i];
        s += x; sq += x * x;
    }
    __shared__ float sh1[8], sh2[8];
    s = warpSum(s); sq = warpSum(sq);
    const int w = threadIdx.x >> 5, l = threadIdx.x & 31;
    if (l == 0) { sh1[w] = s; sh2[w] = sq; }
    __syncthreads();
    if (threadIdx.x == 0) {
        float ts = 0.f, tq = 0.f;
#pragma unroll
        for (int i = 0; i < 8; i++) { ts += sh1[i]; tq += sh2[i]; }
        part[z * 16 + p] = make_float2(ts, tq);
    }
}

__global__ void stats_p2(const float2* __restrict__ part, float* __restrict__ stats, int C)
{
    const int z = blockIdx.x;
    const int l = threadIdx.x;
    float s = 0.f, sq = 0.f;
    if (l < 16) { const float2 v = part[z * 16 + l]; s = v.x; sq = v.y; }
    s = warpSum(s); sq = warpSum(sq);
    if (l == 0) {
        const float invn = 1.f / (float)((long)C * KV);
        const float mean = s * invn;
        const float var  = sq * invn - mean * mean;
        stats[z * 2 + 0] = mean;
        stats[z * 2 + 1] = rsqrtf(var + 1e-5f);
    }
}

__global__ void softmax_kernel(const float* __restrict__ S,
                               __half* __restrict__ PH,
                               __half* __restrict__ PL,
                               const float* __restrict__ stats, int C)
{
    const int row = blockIdx.x;
    const int z = row / C;
    const float inv = stats[z * 2 + 1];
    const float* p = S + (long)row * KV;
    __half* ph = PH + (long)row * KV;
    __half* pl = PL + (long)row * KV;
    const int tid = threadIdx.x;
    const int w = tid >> 5, l = tid & 31;

    __shared__ float sred[8];
    __shared__ float s_mx, s_se;
    __shared__ float se_buf[960];

    float mx = -1e30f;
    for (int i = tid; i < KV; i += 256) mx = fmaxf(mx, p[i]);
    mx = warpMax(mx);
    if (l == 0) sred[w] = mx;
    __syncthreads();
    if (tid == 0) {
        float m = sred[0];
#pragma unroll
        for (int i = 1; i < 8; i++) m = fmaxf(m, sred[i]);
        s_mx = m;
    }
    __syncthreads();
    mx = s_mx;

    float se = 0.f;
    for (int i = tid; i < KV; i += 256) {
        const float e = expf((p[i] - mx) * inv);
        se_buf[i] = e;
        se += e;
    }
    se = warpSum(se);
    __syncthreads();
    if (l == 0) sred[w] = se;
    __syncthreads();
    if (tid == 0) {
        float t = 0.f;
#pragma unroll
        for (int i = 0; i < 8; i++) t += sred[i];
        s_se = 1.f / t;
    }
    __syncthreads();
    const float r = s_se;
    for (int i = tid; i < KV; i += 256) {
        const float v = se_buf[i] * r;
        const __half hb = __float2half_rn(v);
        ph[i] = hb;
        pl[i] = __float2half_rn(v - __half2float(hb));
    }
}

// ---------------------------------------------------------------------------
// Host launch
// ---------------------------------------------------------------------------
static const int DSM192 = 3 * (16384 + 2 * 192 * 128);   // 196,608
static const int DSM128 = 3 * (16384 + 2 * 128 * 128);   // 147,456
static const int DSM64  = 3 * (16384 + 2 * 64 * 128);    //  98,304

struct HTensors { const __half *h, *l; };

static inline void launch_gemm(int NT, bool split, dim3 grid, cudaStream_t st,
                               HTensors A, HTensors B,
                               float* Cf, __half* CH, __half* CL,
                               int M, int N, int K,
                               long sAo, long sAi, long sBo, long sBi, long sC,
                               int hDiv, int nAcc, long accA, long accB, float scale)
{
    if (NT == 192) {
        if (split) {
            cudaFuncSetAttribute(gemm_hf<192, true>, cudaFuncAttributeMaxDynamicSharedMemorySize, DSM192);
            gemm_hf<192, true><<<grid, 256, DSM192, st>>>(A.h, B.h, B.l, Cf, CH, CL,
                M, N, K, sAo, sAi, sBo, sBi, sC, hDiv, nAcc, accA, accB, scale);
        } else {
            cudaFuncSetAttribute(gemm_hf<192, false>, cudaFuncAttributeMaxDynamicSharedMemorySize, DSM192);
            gemm_hf<192, false><<<grid, 256, DSM192, st>>>(A.h, B.h, B.l, Cf, CH, CL,
                M, N, K, sAo, sAi, sBo, sBi, sC, hDiv, nAcc, accA, accB, scale);
        }
    } else if (NT == 128) {
        if (split) {
            cudaFuncSetAttribute(gemm_hf<128, true>, cudaFuncAttributeMaxDynamicSharedMemorySize, DSM128);
            gemm_hf<128, true><<<grid, 256, DSM128, st>>>(A.h, B.h, B.l, Cf, CH, CL,
                M, N, K, sAo, sAi, sBo, sBi, sC, hDiv, nAcc, accA, accB, scale);
        } else {
            cudaFuncSetAttribute(gemm_hf<128, false>, cudaFuncAttributeMaxDynamicSharedMemorySize, DSM128);
            gemm_hf<128, false><<<grid, 256, DSM128, st>>>(A.h, B.h, B.l, Cf, CH, CL,
                M, N, K, sAo, sAi, sBo, sBi, sC, hDiv, nAcc, accA, accB, scale);
        }
    } else {
        if (split) {
            cudaFuncSetAttribute(gemm_hf<64, true>, cudaFuncAttributeMaxDynamicSharedMemorySize, DSM64);
            gemm_hf<64, true><<<grid, 256, DSM64, st>>>(A.h, B.h, B.l, Cf, CH, CL,
                M, N, K, sAo, sAi, sBo, sBi, sC, hDiv, nAcc, accA, accB, scale);
        } else {
            cudaFuncSetAttribute(gemm_hf<64, false>, cudaFuncAttributeMaxDynamicSharedMemorySize, DSM64);
            gemm_hf<64, false><<<grid, 256, DSM64, st>>>(A.h, B.h, B.l, Cf, CH, CL,
                M, N, K, sAo, sAi, sBo, sBi, sC, hDiv, nAcc, accA, accB, scale);
        }
    }
}

// R13-proven stream topology: serial Kt,V on origin; fork after V; 3 created
// streams; 3 joins. Branch order 3,2,1,0 (big branch on origin, early).
struct StreamPack {
    cudaStream_t st[3];
    cudaEvent_t fork, join[3];
    StreamPack() {
        for (int i = 0; i < 3; ++i) {
            cudaStreamCreateWithFlags(&st[i], cudaStreamNonBlocking);
            cudaEventCreateWithFlags(&join[i], cudaEventDisableTiming);
        }
        cudaEventCreateWithFlags(&fork, cudaEventDisableTiming);
    }
};
static StreamPack& sp() { static StreamPack s; return s; }

extern "C" void kernel_launch(void* const* d_in, const int* in_sizes, int n_in,
                              void* d_out, int out_size)
{
    (void)n_in; (void)out_size;

    // ---- input-order detection (dict order has Wq/Wo interleaved) ----
    int ie[4], ieall, iwq[4], iwo[4], iwk, iwv;
    const int SZ_WK   = 4 * 960 * 960;
    const int SZ_EMB1 = 8 * 1024 * 64;
    const int SZ_WO1  = 64 * 64;

    if (in_sizes[0] == SZ_WK) {
        iwk = 0;
        iwo[0] = 1; iwo[1] = 2; iwo[2] = 3; iwo[3] = 4;
        iwq[0] = 5; iwq[1] = 6; iwq[2] = 7; iwq[3] = 8;
        iwv = 9;
        ie[0] = 10; ie[1] = 11; ie[2] = 12; ie[3] = 13;
        ieall = 14;
    } else if (in_sizes[0] == SZ_EMB1 && in_sizes[5] == SZ_WK) {
        ie[0] = 0; ie[1] = 1; ie[2] = 2; ie[3] = 3; ieall = 4;
        iwk = 5;
        iwo[0] = 6; iwo[1] = 7; iwo[2] = 8; iwo[3] = 9;
        iwq[0] = 10; iwq[1] = 11; iwq[2] = 12; iwq[3] = 13;
        iwv = 14;
    } else if (in_sizes[6] == SZ_WO1) {
        ie[0] = 0; ie[1] = 1; ie[2] = 2; ie[3] = 3; ieall = 4;
        iwq[0] = 5;  iwo[0] = 6;
        iwq[1] = 7;  iwo[1] = 8;
        iwq[2] = 9;  iwo[2] = 10;
        iwq[3] = 11; iwo[3] = 12;
        iwk = 13; iwv = 14;
    } else {
        ie[0] = 0; ie[1] = 1; ie[2] = 2; ie[3] = 3; ieall = 4;
        iwq[0] = 5; iwq[1] = 6; iwq[2] = 7; iwq[3] = 8;
        iwo[0] = 9; iwo[1] = 10; iwo[2] = 11; iwo[3] = 12;
        iwk = 13; iwv = 14;
    }

    float* out = (float*)d_out;

    __half *inH, *inL;
    __half *ktH, *ktL, *vH, *vL, *qtH, *qtL, *pHg, *pLg, *cHg, *cLg;
    float *pS, *pSt;
    float2 *pPart;
    cudaGetSymbolAddress((void**)&inH, g_inH);
    cudaGetSymbolAddress((void**)&inL, g_inL);
    cudaGetSymbolAddress((void**)&ktH, g_KtH);
    cudaGetSymbolAddress((void**)&ktL, g_KtL);
    cudaGetSymbolAddress((void**)&vH,  g_VH);
    cudaGetSymbolAddress((void**)&vL,  g_VL);
    cudaGetSymbolAddress((void**)&qtH, g_QtH);
    cudaGetSymbolAddress((void**)&qtL, g_QtL);
    cudaGetSymbolAddress((void**)&pHg, g_PH);
    cudaGetSymbolAddress((void**)&pLg, g_PL);
    cudaGetSymbolAddress((void**)&cHg, g_cH);
    cudaGetSymbolAddress((void**)&cLg, g_cL);
    cudaGetSymbolAddress((void**)&pS,  g_S);
    cudaGetSymbolAddress((void**)&pSt, g_stats);
    cudaGetSymbolAddress((void**)&pPart, g_part);

    const int Cs[4]   = {64, 128, 256, 512};
    const int cumC[4] = {0, 64, 192, 448};

    // ---- single fused conversion over the whole arena (origin stream) ----
    size_t off[15]; int idx[15]; size_t cur = 0; int t = 0;
    for (int i = 0; i < 4; ++i) { idx[t] = ie[i];  off[t] = cur; cur += (size_t)Bb * Nn * Cs[i]; ++t; }
    idx[t] = ieall; off[t] = cur; cur += (size_t)Bb * Nn * KV; ++t;
    for (int i = 0; i < 4; ++i) { idx[t] = iwq[i]; off[t] = cur; cur += (size_t)Hh * Cs[i] * Cs[i]; ++t; }
    idx[t] = iwk; off[t] = cur; cur += (size_t)Hh * KV * KV; ++t;
    idx[t] = iwv; off[t] = cur; cur += (size_t)Hh * KV * KV; ++t;
    for (int i = 0; i < 4; ++i) { idx[t] = iwo[i]; off[t] = cur; cur += (size_t)Cs[i] * Cs[i]; ++t; }

    ConvParams P;
    for (int j = 0; j < 15; ++j) {
        P.src[j]  = (const float*)d_in[idx[j]];
        P.cum4[j] = (long)(off[j] / 4);
    }
    P.cum4[15] = (long)(cur / 4);
    const long total4 = (long)(cur / 4);
    conv_all<<<(unsigned)((total4 + 255) / 256), 256>>>(P, inH, inL, total4);

    HTensors embT[4], embAllT, WqT[4], WkT, WvT, WoT[4];
    for (int i = 0; i < 4; ++i) embT[i] = { inH + off[i], inL + off[i] };
    embAllT = { inH + off[4], inL + off[4] };
    for (int i = 0; i < 4; ++i) WqT[i] = { inH + off[5 + i], inL + off[5 + i] };
    WkT = { inH + off[9],  inL + off[9]  };
    WvT = { inH + off[10], inL + off[10] };
    for (int i = 0; i < 4; ++i) WoT[i] = { inH + off[11 + i], inL + off[11 + i] };

    const float sscale = 0.032274861f;  // 1/sqrt(960)

    // 1) Kt  2) V  (origin stream, serialized; NT=192 3-stage tiles)
    launch_gemm(192, true, dim3(6, 8, Bb * Hh), 0,
                WkT, embAllT, nullptr, ktH, ktL,
                KV, Nn, KV,
                0, (long)KV * KV, (long)Nn * KV, 0, (long)KV * Nn,
                Hh, 1, 0, 0, 1.f);
    launch_gemm(192, true, dim3(5, 8, Bb * Hh), 0,
                embAllT, WvT, nullptr, vH, vL,
                Nn, KV, KV,
                (long)Nn * KV, 0, 0, (long)KV * KV, (long)Nn * KV,
                Hh, 1, 0, 0, 1.f);

    // ---- fork after V: branches on created streams, first branch on origin ----
    StreamPack& S = sp();
    cudaEventRecord(S.fork, 0);
    for (int i = 0; i < 3; ++i) cudaStreamWaitEvent(S.st[i], S.fork, 0);

    long outOff[4];
    {
        long o = 0;
        for (int i = 0; i < 4; ++i) { outOff[i] = o; o += (long)Bb * Nn * Cs[i]; }
    }

    const int order[4] = {3, 2, 1, 0};
    for (int oi = 0; oi < 4; ++oi) {
        const int i = order[oi];
        const int C = Cs[i];
        const int mtC = (C + 127) / 128;
        const int NTC = (C >= 512) ? 128 : ((C >= 128) ? 128 : 64);
        const int ntC = (C + NTC - 1) / NTC;
        cudaStream_t st = (oi == 0) ? (cudaStream_t)0 : S.st[oi - 1];

        __half* qtHb = qtH + (size_t)cumC[i] * 32 * 1024;
        __half* qtLb = qtL + (size_t)cumC[i] * 32 * 1024;
        float*  pSb  = pS  + (size_t)cumC[i] * 32 * 960;
        __half* pHb  = pHg + (size_t)cumC[i] * 32 * 960;
        __half* pLb  = pLg + (size_t)cumC[i] * 32 * 960;
        __half* cHb  = cHg + (size_t)cumC[i] * 8 * 1024;
        __half* cLb  = cLg + (size_t)cumC[i] * 8 * 1024;
        float*  stB  = pSt + (size_t)i * 64;
        float2* ptB  = pPart + (size_t)i * 512;

        // 3) Qt (N=1024 -> 6 tiles of 192)
        launch_gemm(192, true, dim3(6, mtC, Bb * Hh), st,
                    WqT[i], embT[i], nullptr, qtHb, qtLb,
                    C, Nn, C,
                    0, (long)C * C, (long)Nn * C, 0, (long)C * Nn,
                    Hh, 1, 0, 0, 1.f);

        // 4) S (N=960 -> exactly 5 tiles of 192)
        launch_gemm(192, false, dim3(5, mtC, Bb * Hh), st,
                    HTensors{qtHb, qtLb}, HTensors{ktH, ktL}, pSb, nullptr, nullptr,
                    C, KV, Nn,
                    (long)C * Nn, 0, (long)KV * Nn, 0, (long)C * KV,
                    1, 1, 0, 0, sscale);

        // stats (two-phase)
        stats_p1<<<dim3(Bb * Hh, 16), 256, 0, st>>>(pSb, ptB, C);
        stats_p2<<<Bb * Hh, 32, 0, st>>>(ptB, stB, C);

        // softmax -> split probs
        softmax_kernel<<<Bb * Hh * C, 256, 0, st>>>(pSb, pHb, pLb, stB, C);

        // 5) ctx
        launch_gemm(NTC, true, dim3(ntC, 8, Bb), st,
                    HTensors{vH, vL}, HTensors{pHb, pLb}, nullptr, cHb, cLb,
                    Nn, C, KV,
                    (long)Hh * Nn * KV, 0, (long)Hh * C * KV, 0, (long)Nn * C,
                    1, Hh, (long)Nn * KV, (long)C * KV, 0.25f);

        // 6) out
        launch_gemm(NTC, false, dim3(ntC, 8, Bb), st,
                    HTensors{cHb, cLb}, WoT[i], out + outOff[i], nullptr, nullptr,
                    Nn, C, C,
                    (long)Nn * C, 0, 0, 0, (long)Nn * C,
                    1, 1, 0, 0, 1.f);
    }

    // ---- join back to origin stream ----
    for (int i = 0; i < 3; ++i) {
        cudaEventRecord(S.join[i], S.st[i]);
        cudaStreamWaitEvent(0, S.join[i], 0);
    }
}

// round 16
// speedup vs baseline: 1.1160x; 1.1160x over previous
#include <cuda_runtime.h>
#include <cuda_fp16.h>
#include <math.h>
#include <stdint.h>

namespace {
constexpr int Bb = 8;
constexpr int Hh = 4;
constexpr int Nn = 1024;
constexpr int KV = 960;
constexpr int CSUM = 960;   // 64+128+256+512
}

// ---------------------------------------------------------------------------
// Device-global scratch (allocation-free). Per-branch private regions.
// ---------------------------------------------------------------------------
constexpr size_t IN_ARENA = 24842240;
__device__ __half g_inH[IN_ARENA];
__device__ __half g_inL[IN_ARENA];

__device__ __half g_KtH[(size_t)Bb * Hh * KV * Nn];
__device__ __half g_KtL[(size_t)Bb * Hh * KV * Nn];
__device__ __half g_VH [(size_t)Bb * Hh * Nn * KV];
__device__ __half g_VL [(size_t)Bb * Hh * Nn * KV];
__device__ __half g_QtH[(size_t)Bb * Hh * CSUM * Nn];
__device__ __half g_QtL[(size_t)Bb * Hh * CSUM * Nn];
__device__ float  g_S  [(size_t)Bb * Hh * CSUM * KV];
__device__ __half g_PH [(size_t)Bb * Hh * CSUM * KV];
__device__ __half g_PL [(size_t)Bb * Hh * CSUM * KV];
__device__ __half g_cH [(size_t)Bb * Nn * CSUM];
__device__ __half g_cL [(size_t)Bb * Nn * CSUM];
__device__ float  g_stats[4 * Bb * Hh * 2];
__device__ float2 g_part[4 * Bb * Hh * 16];

__device__ __forceinline__ uint32_t smem_u32(const void* p) {
    uint32_t a;
    asm("{ .reg .u64 t; cvta.to.shared.u64 t, %1; cvt.u32.u64 %0, t; }" : "=r"(a) : "l"(p));
    return a;
}

#define LDMX4(r, addr)                                                          \
    asm volatile("ldmatrix.sync.aligned.m8n8.x4.shared.b16 {%0,%1,%2,%3}, [%4];" \
        : "=r"((r)[0]), "=r"((r)[1]), "=r"((r)[2]), "=r"((r)[3]) : "r"(addr))
#define MMA16816(d, a, b)                                                       \
    asm volatile("mma.sync.aligned.m16n8k16.row.col.f32.f16.f16.f32 "           \
        "{%0,%1,%2,%3}, {%4,%5,%6,%7}, {%8,%9}, {%0,%1,%2,%3};"                 \
        : "+f"((d)[0]), "+f"((d)[1]), "+f"((d)[2]), "+f"((d)[3])                \
        : "r"((a)[0]), "r"((a)[1]), "r"((a)[2]), "r"((a)[3]),                   \
          "r"((b)[0]), "r"((b)[1]))
#define CP16(dst, src, vsz)                                                     \
    asm volatile("cp.async.ca.shared.global [%0], [%1], 16, %2;"                \
        :: "r"(dst), "l"(src), "r"(vsz) : "memory")
#define CP_COMMIT asm volatile("cp.async.commit_group;" ::: "memory")
#define CP_WAIT1  asm volatile("cp.async.wait_group 1;" ::: "memory")
#define CP_WAIT0  asm volatile("cp.async.wait_group 0;" ::: "memory")

// split fp32 pair -> fp16 hi pair + fp16 lo (residual) pair
__device__ __forceinline__ void splitf16(float x, float y, uint32_t& h, uint32_t& l) {
    __half2 hh = __floats2half2_rn(x, y);
    const float hx = __low2float(hh);
    const float hy = __high2float(hh);
    __half2 ll = __floats2half2_rn(x - hx, y - hy);
    h = *reinterpret_cast<uint32_t*>(&hh);
    l = *reinterpret_cast<uint32_t*>(&ll);
}

// ---------------------------------------------------------------------------
// Single fused input conversion over the whole arena.
// ---------------------------------------------------------------------------
struct ConvParams {
    const float* src[15];
    long         cum4[16];
};

__global__ void conv_all(ConvParams P, __half* __restrict__ hi,
                         __half* __restrict__ lo, long total4)
{
    const long i = (long)blockIdx.x * blockDim.x + threadIdx.x;
    if (i >= total4) return;
    int j = 0;
#pragma unroll
    for (int k = 1; k < 15; ++k) if (i >= P.cum4[k]) j = k;
    const float4 v = reinterpret_cast<const float4*>(P.src[j])[i - P.cum4[j]];
    uint32_t h01, l01, h23, l23;
    splitf16(v.x, v.y, h01, l01);
    splitf16(v.z, v.w, h23, l23);
    reinterpret_cast<uint2*>(hi)[i] = make_uint2(h01, h23);
    reinterpret_cast<uint2*>(lo)[i] = make_uint2(l01, l23);
}

// ---------------------------------------------------------------------------
// NT GEMM: fp16 split, 2-product (A-hi x B-hi + A-hi x B-lo). A-lo never read.
// MMA inner loop split into two passes (all bh, then all bl) so each
// accumulator's RAW pair sits 32 MMAs apart instead of back-to-back.
// ---------------------------------------------------------------------------
template<int NT, bool SPLIT_OUT>
__global__ __launch_bounds__(256)
void gemm_hf(const __half* __restrict__ AH,
             const __half* __restrict__ BH, const __half* __restrict__ BL,
             float* __restrict__ Cf,
             __half* __restrict__ CH, __half* __restrict__ CL,
             int M, int N, int K,
             long sAo, long sAi, long sBo, long sBi, long sC,
             int hDiv, int nAcc, long accA, long accB, float scale)
{
    constexpr int NN    = NT / 32;
    constexpr int BPU   = NT * 8;
    constexpr int UNITS = 1024 + 2 * BPU;
    constexpr int NU    = UNITS / 256;
    constexpr int STAGE = 16384 + 2 * NT * 128;
    constexpr int NST   = (NT >= 256) ? 2 : 3;

    extern __shared__ __align__(128) char smdyn[];
    const uint32_t su = smem_u32(smdyn);

    const int tid  = threadIdx.x;
    const int lane = tid & 31;
    const int wid  = tid >> 5;
    const int wm   = (wid >> 2) * 64;
    const int wn   = (wid & 3) * (NT / 4);

    const int m0 = blockIdx.y * 128;
    const int n0 = blockIdx.x * NT;
    const int z  = blockIdx.z;

    const long aOff = (long)(z / hDiv) * sAo + (long)(z % hDiv) * sAi;
    const long bOff = (long)(z / hDiv) * sBo + (long)(z % hDiv) * sBi;
    const __half* AHb = AH + aOff;
    const __half* BHb = BH + bOff;
    const __half* BLb = BL + bOff;
    const int mRem = M - m0;

    const int aRow  = (lane & 7) + ((lane >> 3) & 1) * 8;
    const int aSlab = (lane >> 4) * 16;

    float acc[4][NN][4];
#pragma unroll
    for (int i = 0; i < 4; i++)
#pragma unroll
        for (int j = 0; j < NN; j++)
#pragma unroll
            for (int r = 0; r < 4; r++) acc[i][j][r] = 0.f;

    const int kChunks = K >> 6;
    const int nChunks = nAcc * kChunks;

    auto issue = [&](int c) {
        const int hn = c / kChunks;
        const int k0 = (c % kChunks) << 6;
        const __half* pa  = AHb + (long)hn * accA;
        const __half* pb[2] = { BHb + (long)hn * accB, BLb + (long)hn * accB };
        const uint32_t buf = su + (uint32_t)(c % NST) * STAGE;
#pragma unroll
        for (int j = 0; j < NU; ++j) {
            const int u = tid + j * 256;
            const __half* src;
            uint32_t dst;
            int vsz;
            if (u < 1024) {
                const int row = u >> 3, g = u & 7;
                const int rr = (row < mRem) ? row : 0;
                vsz = (row < mRem) ? 16 : 0;
                src = pa + (long)(m0 + rr) * K + k0 + g * 8;
                dst = buf + (uint32_t)row * 128u + (uint32_t)((g ^ (row & 7)) << 4);
            } else {
                const int ub = u - 1024;
                const int pl = ub / BPU, w = ub % BPU;
                const int row = w >> 3, g = w & 7;
                const int rr = (n0 + row < N) ? row : 0;
                vsz = (n0 + row < N) ? 16 : 0;
                src = pb[pl] + (long)(n0 + rr) * K + k0 + g * 8;
                dst = buf + 16384u + (uint32_t)pl * (uint32_t)(NT * 128)
                          + (uint32_t)row * 128u + (uint32_t)((g ^ (row & 7)) << 4);
            }
            CP16(dst, src, vsz);
        }
    };

    issue(0); CP_COMMIT;
    if (nChunks > 1) { issue(1); CP_COMMIT; }

    for (int c = 0; c < nChunks; ++c) {
        if (c + 1 < nChunks) { CP_WAIT1; } else { CP_WAIT0; }
        __syncthreads();
        if (NST == 3 && c + 2 < nChunks) { issue(c + 2); CP_COMMIT; }

        const uint32_t buf = su + (uint32_t)(c % NST) * STAGE;
        const uint32_t aHi = buf;
        const uint32_t bHi = buf + 16384;
        const uint32_t bLo = buf + 16384 + NT * 128;

#pragma unroll
        for (int ks = 0; ks < 4; ++ks) {
            const int cbase = ks * 32;
            uint32_t ah[4][4];
#pragma unroll
            for (int mt = 0; mt < 4; ++mt) {
                const int row = wm + mt * 16 + aRow;
                const int cb  = cbase + aSlab;
                const uint32_t off = (uint32_t)row * 128u
                                   + (uint32_t)((((cb >> 4) ^ (row & 7))) << 4);
                LDMX4(ah[mt], aHi + off);
            }
            uint32_t bh[NN][2], bl[NN][2];
#pragma unroll
            for (int p = 0; p < NN / 2; ++p) {
                const int mr  = lane >> 3;
                const int row = wn + p * 16 + (mr >> 1) * 8 + (lane & 7);
                const int cb  = cbase + (mr & 1) * 16;
                const uint32_t off = (uint32_t)row * 128u
                                   + (uint32_t)((((cb >> 4) ^ (row & 7))) << 4);
                uint32_t q[4];
                LDMX4(q, bHi + off);
                bh[2*p][0] = q[0]; bh[2*p][1] = q[1];
                bh[2*p+1][0] = q[2]; bh[2*p+1][1] = q[3];
                LDMX4(q, bLo + off);
                bl[2*p][0] = q[0]; bl[2*p][1] = q[1];
                bl[2*p+1][0] = q[2]; bl[2*p+1][1] = q[3];
            }
            // pass 1: all hi products (independent accumulators)
#pragma unroll
            for (int mt = 0; mt < 4; ++mt)
#pragma unroll
                for (int nt = 0; nt < NN; ++nt)
                    MMA16816(acc[mt][nt], ah[mt], bh[nt]);
            // pass 2: all lo products (RAW distance = 4*NN MMAs)
#pragma unroll
            for (int mt = 0; mt < 4; ++mt)
#pragma unroll
                for (int nt = 0; nt < NN; ++nt)
                    MMA16816(acc[mt][nt], ah[mt], bl[nt]);
        }

        if (NST == 2) {
            __syncthreads();
            if (c + 2 < nChunks) { issue(c + 2); CP_COMMIT; }
        }
    }

    // ---- epilogue ----
    float* Cfp = SPLIT_OUT ? nullptr : (Cf + (long)z * sC);
    __half* CHp = SPLIT_OUT ? (CH + (long)z * sC) : nullptr;
    __half* CLp = SPLIT_OUT ? (CL + (long)z * sC) : nullptr;

#pragma unroll
    for (int mt = 0; mt < 4; ++mt) {
#pragma unroll
        for (int nt = 0; nt < NN; ++nt) {
            const int m1 = m0 + wm + mt * 16 + (lane >> 2);
            const int n  = n0 + wn + nt * 8 + (lane & 3) * 2;
            if (n >= N) continue;
#pragma unroll
            for (int half = 0; half < 2; ++half) {
                const int m = m1 + half * 8;
                if (m >= M) continue;
                const float x = acc[mt][nt][half * 2 + 0] * scale;
                const float y = acc[mt][nt][half * 2 + 1] * scale;
                if (SPLIT_OUT) {
                    uint32_t h, l;
                    splitf16(x, y, h, l);
                    *reinterpret_cast<uint32_t*>(CHp + (long)m * N + n) = h;
                    *reinterpret_cast<uint32_t*>(CLp + (long)m * N + n) = l;
                } else {
                    *reinterpret_cast<float2*>(Cfp + (long)m * N + n) = make_float2(x, y);
                }
            }
        }
    }
}

// ---------------------------------------------------------------------------
// Two-phase instance-norm stats + softmax (emits split probs)
// ---------------------------------------------------------------------------
__inline__ __device__ float warpSum(float v) {
#pragma unroll
    for (int o = 16; o; o >>= 1) v += __shfl_xor_sync(0xffffffffu, v, o);
    return v;
}
__inline__ __device__ float warpMax(float v) {
#pragma unroll
    for (int o = 16; o; o >>= 1) v = fmaxf(v, __shfl_xor_sync(0xffffffffu, v, o));
    return v;
}

__global__ void stats_p1(const float* __restrict__ S, float2* __restrict__ part, int C)
{
    const int z = blockIdx.x, p = blockIdx.y;
    const long n = (long)C * KV;
    const long len = (n + 15) >> 4;
    const long lo = (long)p * len;
    const long hi = (lo + len < n) ? lo + len : n;
    const float* base = S + (long)z * n;
    float s = 0.f, sq = 0.f;
    for (long i = lo + threadIdx.x; i < hi; i += blockDim.x) {
        const float x = base[i];
        s += x; sq += x * x;
    }
    __shared__ float sh1[8], sh2[8];
    s = warpSum(s); sq = warpSum(sq);
    const int w = threadIdx.x >> 5, l = threadIdx.x & 31;
    if (l == 0) { sh1[w] = s; sh2[w] = sq; }
    __syncthreads();
    if (threadIdx.x == 0) {
        float ts = 0.f, tq = 0.f;
#pragma unroll
        for (int i = 0; i < 8; i++) { ts += sh1[i]; tq += sh2[i]; }
        part[z * 16 + p] = make_float2(ts, tq);
    }
}

__global__ void stats_p2(const float2* __restrict__ part, float* __restrict__ stats, int C)
{
    const int z = blockIdx.x;
    const int l = threadIdx.x;
    float s = 0.f, sq = 0.f;
    if (l < 16) { const float2 v = part[z * 16 + l]; s = v.x; sq = v.y; }
    s = warpSum(s); sq = warpSum(sq);
    if (l == 0) {
        const float invn = 1.f / (float)((long)C * KV);
        const float mean = s * invn;
        const float var  = sq * invn - mean * mean;
        stats[z * 2 + 0] = mean;
        stats[z * 2 + 1] = rsqrtf(var + 1e-5f);
    }
}

__global__ void softmax_kernel(const float* __restrict__ S,
                               __half* __restrict__ PH,
                               __half* __restrict__ PL,
                               const float* __restrict__ stats, int C)
{
    const int row = blockIdx.x;
    const int z = row / C;
    const float inv = stats[z * 2 + 1];
    const float* p = S + (long)row * KV;
    __half* ph = PH + (long)row * KV;
    __half* pl = PL + (long)row * KV;
    const int tid = threadIdx.x;
    const int w = tid >> 5, l = tid & 31;

    __shared__ float sred[8];
    __shared__ float s_mx, s_se;
    __shared__ float se_buf[960];

    float mx = -1e30f;
    for (int i = tid; i < KV; i += 256) mx = fmaxf(mx, p[i]);
    mx = warpMax(mx);
    if (l == 0) sred[w] = mx;
    __syncthreads();
    if (tid == 0) {
        float m = sred[0];
#pragma unroll
        for (int i = 1; i < 8; i++) m = fmaxf(m, sred[i]);
        s_mx = m;
    }
    __syncthreads();
    mx = s_mx;

    float se = 0.f;
    for (int i = tid; i < KV; i += 256) {
        const float e = expf((p[i] - mx) * inv);
        se_buf[i] = e;
        se += e;
    }
    se = warpSum(se);
    __syncthreads();
    if (l == 0) sred[w] = se;
    __syncthreads();
    if (tid == 0) {
        float t = 0.f;
#pragma unroll
        for (int i = 0; i < 8; i++) t += sred[i];
        s_se = 1.f / t;
    }
    __syncthreads();
    const float r = s_se;
    for (int i = tid; i < KV; i += 256) {
        const float v = se_buf[i] * r;
        const __half hb = __float2half_rn(v);
        ph[i] = hb;
        pl[i] = __float2half_rn(v - __half2float(hb));
    }
}

// ---------------------------------------------------------------------------
// Host launch
// ---------------------------------------------------------------------------
static const int DSM256 = 2 * (16384 + 2 * 256 * 128);   // 163,840
static const int DSM128 = 3 * (16384 + 2 * 128 * 128);   // 147,456
static const int DSM64  = 3 * (16384 + 2 * 64 * 128);    //  98,304

struct HTensors { const __half *h, *l; };

static inline void launch_gemm(int NT, bool split, dim3 grid, cudaStream_t st,
                               HTensors A, HTensors B,
                               float* Cf, __half* CH, __half* CL,
                               int M, int N, int K,
                               long sAo, long sAi, long sBo, long sBi, long sC,
                               int hDiv, int nAcc, long accA, long accB, float scale)
{
    if (NT == 256) {
        if (split) {
            cudaFuncSetAttribute(gemm_hf<256, true>, cudaFuncAttributeMaxDynamicSharedMemorySize, DSM256);
            gemm_hf<256, true><<<grid, 256, DSM256, st>>>(A.h, B.h, B.l, Cf, CH, CL,
                M, N, K, sAo, sAi, sBo, sBi, sC, hDiv, nAcc, accA, accB, scale);
        } else {
            cudaFuncSetAttribute(gemm_hf<256, false>, cudaFuncAttributeMaxDynamicSharedMemorySize, DSM256);
            gemm_hf<256, false><<<grid, 256, DSM256, st>>>(A.h, B.h, B.l, Cf, CH, CL,
                M, N, K, sAo, sAi, sBo, sBi, sC, hDiv, nAcc, accA, accB, scale);
        }
    } else if (NT == 128) {
        if (split) {
            cudaFuncSetAttribute(gemm_hf<128, true>, cudaFuncAttributeMaxDynamicSharedMemorySize, DSM128);
            gemm_hf<128, true><<<grid, 256, DSM128, st>>>(A.h, B.h, B.l, Cf, CH, CL,
                M, N, K, sAo, sAi, sBo, sBi, sC, hDiv, nAcc, accA, accB, scale);
        } else {
            cudaFuncSetAttribute(gemm_hf<128, false>, cudaFuncAttributeMaxDynamicSharedMemorySize, DSM128);
            gemm_hf<128, false><<<grid, 256, DSM128, st>>>(A.h, B.h, B.l, Cf, CH, CL,
                M, N, K, sAo, sAi, sBo, sBi, sC, hDiv, nAcc, accA, accB, scale);
        }
    } else {
        if (split) {
            cudaFuncSetAttribute(gemm_hf<64, true>, cudaFuncAttributeMaxDynamicSharedMemorySize, DSM64);
            gemm_hf<64, true><<<grid, 256, DSM64, st>>>(A.h, B.h, B.l, Cf, CH, CL,
                M, N, K, sAo, sAi, sBo, sBi, sC, hDiv, nAcc, accA, accB, scale);
        } else {
            cudaFuncSetAttribute(gemm_hf<64, false>, cudaFuncAttributeMaxDynamicSharedMemorySize, DSM64);
            gemm_hf<64, false><<<grid, 256, DSM64, st>>>(A.h, B.h, B.l, Cf, CH, CL,
                M, N, K, sAo, sAi, sBo, sBi, sC, hDiv, nAcc, accA, accB, scale);
        }
    }
}

// R13-proven stream topology: serial Kt,V on origin; fork after V; 3 created
// streams; 3 joins; branch 0 on origin.
struct StreamPack {
    cudaStream_t st[3];
    cudaEvent_t fork, join[3];
    StreamPack() {
        for (int i = 0; i < 3; ++i) {
            cudaStreamCreateWithFlags(&st[i], cudaStreamNonBlocking);
            cudaEventCreateWithFlags(&join[i], cudaEventDisableTiming);
        }
        cudaEventCreateWithFlags(&fork, cudaEventDisableTiming);
    }
};
static StreamPack& sp() { static StreamPack s; return s; }

extern "C" void kernel_launch(void* const* d_in, const int* in_sizes, int n_in,
                              void* d_out, int out_size)
{
    (void)n_in; (void)out_size;

    // ---- input-order detection (dict order has Wq/Wo interleaved) ----
    int ie[4], ieall, iwq[4], iwo[4], iwk, iwv;
    const int SZ_WK   = 4 * 960 * 960;
    const int SZ_EMB1 = 8 * 1024 * 64;
    const int SZ_WO1  = 64 * 64;

    if (in_sizes[0] == SZ_WK) {
        iwk = 0;
        iwo[0] = 1; iwo[1] = 2; iwo[2] = 3; iwo[3] = 4;
        iwq[0] = 5; iwq[1] = 6; iwq[2] = 7; iwq[3] = 8;
        iwv = 9;
        ie[0] = 10; ie[1] = 11; ie[2] = 12; ie[3] = 13;
        ieall = 14;
    } else if (in_sizes[0] == SZ_EMB1 && in_sizes[5] == SZ_WK) {
        ie[0] = 0; ie[1] = 1; ie[2] = 2; ie[3] = 3; ieall = 4;
        iwk = 5;
        iwo[0] = 6; iwo[1] = 7; iwo[2] = 8; iwo[3] = 9;
        iwq[0] = 10; iwq[1] = 11; iwq[2] = 12; iwq[3] = 13;
        iwv = 14;
    } else if (in_sizes[6] == SZ_WO1) {
        ie[0] = 0; ie[1] = 1; ie[2] = 2; ie[3] = 3; ieall = 4;
        iwq[0] = 5;  iwo[0] = 6;
        iwq[1] = 7;  iwo[1] = 8;
        iwq[2] = 9;  iwo[2] = 10;
        iwq[3] = 11; iwo[3] = 12;
        iwk = 13; iwv = 14;
    } else {
        ie[0] = 0; ie[1] = 1; ie[2] = 2; ie[3] = 3; ieall = 4;
        iwq[0] = 5; iwq[1] = 6; iwq[2] = 7; iwq[3] = 8;
        iwo[0] = 9; iwo[1] = 10; iwo[2] = 11; iwo[3] = 12;
        iwk = 13; iwv = 14;
    }

    float* out = (float*)d_out;

    __half *inH, *inL;
    __half *ktH, *ktL, *vH, *vL, *qtH, *qtL, *pHg, *pLg, *cHg, *cLg;
    float *pS, *pSt;
    float2 *pPart;
    cudaGetSymbolAddress((void**)&inH, g_inH);
    cudaGetSymbolAddress((void**)&inL, g_inL);
    cudaGetSymbolAddress((void**)&ktH, g_KtH);
    cudaGetSymbolAddress((void**)&ktL, g_KtL);
    cudaGetSymbolAddress((void**)&vH,  g_VH);
    cudaGetSymbolAddress((void**)&vL,  g_VL);
    cudaGetSymbolAddress((void**)&qtH, g_QtH);
    cudaGetSymbolAddress((void**)&qtL, g_QtL);
    cudaGetSymbolAddress((void**)&pHg, g_PH);
    cudaGetSymbolAddress((void**)&pLg, g_PL);
    cudaGetSymbolAddress((void**)&cHg, g_cH);
    cudaGetSymbolAddress((void**)&cLg, g_cL);
    cudaGetSymbolAddress((void**)&pS,  g_S);
    cudaGetSymbolAddress((void**)&pSt, g_stats);
    cudaGetSymbolAddress((void**)&pPart, g_part);

    const int Cs[4]   = {64, 128, 256, 512};
    const int cumC[4] = {0, 64, 192, 448};

    // ---- single fused conversion over the whole arena (origin stream) ----
    size_t off[15]; int idx[15]; size_t cur = 0; int t = 0;
    for (int i = 0; i < 4; ++i) { idx[t] = ie[i];  off[t] = cur; cur += (size_t)Bb * Nn * Cs[i]; ++t; }
    idx[t] = ieall; off[t] = cur; cur += (size_t)Bb * Nn * KV; ++t;
    for (int i = 0; i < 4; ++i) { idx[t] = iwq[i]; off[t] = cur; cur += (size_t)Hh * Cs[i] * Cs[i]; ++t; }
    idx[t] = iwk; off[t] = cur; cur += (size_t)Hh * KV * KV; ++t;
    idx[t] = iwv; off[t] = cur; cur += (size_t)Hh * KV * KV; ++t;
    for (int i = 0; i < 4; ++i) { idx[t] = iwo[i]; off[t] = cur; cur += (size_t)Cs[i] * Cs[i]; ++t; }

    ConvParams P;
    for (int j = 0; j < 15; ++j) {
        P.src[j]  = (const float*)d_in[idx[j]];
        P.cum4[j] = (long)(off[j] / 4);
    }
    P.cum4[15] = (long)(cur / 4);
    const long total4 = (long)(cur / 4);
    conv_all<<<(unsigned)((total4 + 255) / 256), 256>>>(P, inH, inL, total4);

    HTensors embT[4], embAllT, WqT[4], WkT, WvT, WoT[4];
    for (int i = 0; i < 4; ++i) embT[i] = { inH + off[i], inL + off[i] };
    embAllT = { inH + off[4], inL + off[4] };
    for (int i = 0; i < 4; ++i) WqT[i] = { inH + off[5 + i], inL + off[5 + i] };
    WkT = { inH + off[9],  inL + off[9]  };
    WvT = { inH + off[10], inL + off[10] };
    for (int i = 0; i < 4; ++i) WoT[i] = { inH + off[11 + i], inL + off[11 + i] };

    const float sscale = 0.032274861f;  // 1/sqrt(960)

    // 1) Kt  2) V  (origin stream, serialized; NT=256 tiles)
    launch_gemm(256, true, dim3(4, 8, Bb * Hh), 0,
                WkT, embAllT, nullptr, ktH, ktL,
                KV, Nn, KV,
                0, (long)KV * KV, (long)Nn * KV, 0, (long)KV * Nn,
                Hh, 1, 0, 0, 1.f);
    launch_gemm(256, true, dim3(4, 8, Bb * Hh), 0,
                embAllT, WvT, nullptr, vH, vL,
                Nn, KV, KV,
                (long)Nn * KV, 0, 0, (long)KV * KV, (long)Nn * KV,
                Hh, 1, 0, 0, 1.f);

    // ---- fork after V: branches 1..3 on created streams, branch 0 on origin ----
    StreamPack& S = sp();
    cudaEventRecord(S.fork, 0);
    for (int i = 0; i < 3; ++i) cudaStreamWaitEvent(S.st[i], S.fork, 0);

    long outOff[4];
    {
        long o = 0;
        for (int i = 0; i < 4; ++i) { outOff[i] = o; o += (long)Bb * Nn * Cs[i]; }
    }

    for (int i = 0; i < 4; ++i) {
        const int C = Cs[i];
        const int mtC = (C + 127) / 128;
        const int NTC = (C >= 512) ? 256 : ((C >= 128) ? 128 : 64);
        const int ntC = (C + NTC - 1) / NTC;
        cudaStream_t st = (i == 0) ? (cudaStream_t)0 : S.st[i - 1];

        __half* qtHb = qtH + (size_t)cumC[i] * 32 * 1024;
        __half* qtLb = qtL + (size_t)cumC[i] * 32 * 1024;
        float*  pSb  = pS  + (size_t)cumC[i] * 32 * 960;
        __half* pHb  = pHg + (size_t)cumC[i] * 32 * 960;
        __half* pLb  = pLg + (size_t)cumC[i] * 32 * 960;
        __half* cHb  = cHg + (size_t)cumC[i] * 8 * 1024;
        __half* cLb  = cLg + (size_t)cumC[i] * 8 * 1024;
        float*  stB  = pSt + (size_t)i * 64;
        float2* ptB  = pPart + (size_t)i * 512;

        // 3) Qt
        launch_gemm(256, true, dim3(4, mtC, Bb * Hh), st,
                    WqT[i], embT[i], nullptr, qtHb, qtLb,
                    C, Nn, C,
                    0, (long)C * C, (long)Nn * C, 0, (long)C * Nn,
                    Hh, 1, 0, 0, 1.f);

        // 4) S
        launch_gemm(256, false, dim3(4, mtC, Bb * Hh), st,
                    HTensors{qtHb, qtLb}, HTensors{ktH, ktL}, pSb, nullptr, nullptr,
                    C, KV, Nn,
                    (long)C * Nn, 0, (long)KV * Nn, 0, (long)C * KV,
                    1, 1, 0, 0, sscale);

        // stats (two-phase)
        stats_p1<<<dim3(Bb * Hh, 16), 256, 0, st>>>(pSb, ptB, C);
        stats_p2<<<Bb * Hh, 32, 0, st>>>(ptB, stB, C);

        // softmax -> split probs
        softmax_kernel<<<Bb * Hh * C, 256, 0, st>>>(pSb, pHb, pLb, stB, C);

        // 5) ctx
        launch_gemm(NTC, true, dim3(ntC, 8, Bb), st,
                    HTensors{vH, vL}, HTensors{pHb, pLb}, nullptr, cHb, cLb,
                    Nn, C, KV,
                    (long)Hh * Nn * KV, 0, (long)Hh * C * KV, 0, (long)Nn * C,
                    1, Hh, (long)Nn * KV, (long)C * KV, 0.25f);

        // 6) out
        launch_gemm(NTC, false, dim3(ntC, 8, Bb), st,
                    HTensors{cHb, cLb}, WoT[i], out + outOff[i], nullptr, nullptr,
                    Nn, C, C,
                    (long)Nn * C, 0, 0, 0, (long)Nn * C,
                    1, 1, 0, 0, 1.f);
    }

    // ---- join back to origin stream ----
    for (int i = 0; i < 3; ++i) {
        cudaEventRecord(S.join[i], S.st[i]);
        cudaStreamWaitEvent(0, S.join[i], 0);
    }
}

// round 17
// speedup vs baseline: 1.6893x; 1.5137x over previous
#include <cuda_runtime.h>
#include <cuda_fp16.h>
#include <math.h>
#include <stdint.h>

namespace {
constexpr int Bb = 8;
constexpr int Hh = 4;
constexpr int Nn = 1024;
constexpr int KV = 960;
constexpr int CSUM = 960;   // 64+128+256+512
}

// ---------------------------------------------------------------------------
// Device-global scratch. Intermediates are hi-only now (lo planes were dead).
// ---------------------------------------------------------------------------
constexpr size_t IN_ARENA = 24842240;
__device__ __half g_inH[IN_ARENA];
__device__ __half g_inL[IN_ARENA];

__device__ __half g_KtH[(size_t)Bb * Hh * KV * Nn];
__device__ __half g_VH [(size_t)Bb * Hh * Nn * KV];
__device__ __half g_QtH[(size_t)Bb * Hh * CSUM * Nn];
__device__ float  g_S  [(size_t)Bb * Hh * CSUM * KV];
__device__ __half g_PH [(size_t)Bb * Hh * CSUM * KV];
__device__ __half g_cH [(size_t)Bb * Nn * CSUM];
__device__ float  g_stats[4 * Bb * Hh * 2];
__device__ float2 g_part[4 * Bb * Hh * 16];

__device__ __forceinline__ uint32_t smem_u32(const void* p) {
    uint32_t a;
    asm("{ .reg .u64 t; cvta.to.shared.u64 t, %1; cvt.u32.u64 %0, t; }" : "=r"(a) : "l"(p));
    return a;
}

#define LDMX4(r, addr)                                                          \
    asm volatile("ldmatrix.sync.aligned.m8n8.x4.shared.b16 {%0,%1,%2,%3}, [%4];" \
        : "=r"((r)[0]), "=r"((r)[1]), "=r"((r)[2]), "=r"((r)[3]) : "r"(addr))
#define MMA16816(d, a, b)                                                       \
    asm volatile("mma.sync.aligned.m16n8k16.row.col.f32.f16.f16.f32 "           \
        "{%0,%1,%2,%3}, {%4,%5,%6,%7}, {%8,%9}, {%0,%1,%2,%3};"                 \
        : "+f"((d)[0]), "+f"((d)[1]), "+f"((d)[2]), "+f"((d)[3])                \
        : "r"((a)[0]), "r"((a)[1]), "r"((a)[2]), "r"((a)[3]),                   \
          "r"((b)[0]), "r"((b)[1]))
#define CP16(dst, src, vsz)                                                     \
    asm volatile("cp.async.ca.shared.global [%0], [%1], 16, %2;"                \
        :: "r"(dst), "l"(src), "r"(vsz) : "memory")
#define CP_COMMIT asm volatile("cp.async.commit_group;" ::: "memory")
#define CP_WAIT1  asm volatile("cp.async.wait_group 1;" ::: "memory")
#define CP_WAIT0  asm volatile("cp.async.wait_group 0;" ::: "memory")

// split fp32 pair -> fp16 hi pair + fp16 lo (residual) pair
__device__ __forceinline__ void splitf16(float x, float y, uint32_t& h, uint32_t& l) {
    __half2 hh = __floats2half2_rn(x, y);
    const float hx = __low2float(hh);
    const float hy = __high2float(hh);
    __half2 ll = __floats2half2_rn(x - hx, y - hy);
    h = *reinterpret_cast<uint32_t*>(&hh);
    l = *reinterpret_cast<uint32_t*>(&ll);
}

// ---------------------------------------------------------------------------
// Single fused input conversion over the whole arena.
// ---------------------------------------------------------------------------
struct ConvParams {
    const float* src[15];
    long         cum4[16];
};

__global__ void conv_all(ConvParams P, __half* __restrict__ hi,
                         __half* __restrict__ lo, long total4)
{
    const long i = (long)blockIdx.x * blockDim.x + threadIdx.x;
    if (i >= total4) return;
    int j = 0;
#pragma unroll
    for (int k = 1; k < 15; ++k) if (i >= P.cum4[k]) j = k;
    const float4 v = reinterpret_cast<const float4*>(P.src[j])[i - P.cum4[j]];
    uint32_t h01, l01, h23, l23;
    splitf16(v.x, v.y, h01, l01);
    splitf16(v.z, v.w, h23, l23);
    reinterpret_cast<uint2*>(hi)[i] = make_uint2(h01, h23);
    reinterpret_cast<uint2*>(lo)[i] = make_uint2(l01, l23);
}

// ---------------------------------------------------------------------------
// NT GEMM, fp16. TWOP: A_hi·(B_hi + B_lo); else single product A_hi·B_hi.
// OMODE 0 = fp32 output, 1 = fp16 hi-only output.
// 3-stage cp.async pipeline (2-stage only for TWOP @ NT=256).
// ---------------------------------------------------------------------------
template<int NT, bool TWOP, int OMODE>
__global__ __launch_bounds__(256)
void gemm_hf(const __half* __restrict__ AH,
             const __half* __restrict__ BH, const __half* __restrict__ BL,
             float* __restrict__ Cf, __half* __restrict__ CH,
             int M, int N, int K,
             long sAo, long sAi, long sBo, long sBi, long sC,
             int hDiv, int nAcc, long accA, long accB, float scale)
{
    constexpr int NN    = NT / 32;
    constexpr int NPL   = TWOP ? 2 : 1;
    constexpr int BPU   = NT * 8;
    constexpr int UNITS = 1024 + NPL * BPU;
    constexpr int NU    = UNITS / 256;
    constexpr int STAGE = 16384 + NPL * NT * 128;
    constexpr int NST   = (TWOP && NT >= 256) ? 2 : 3;

    extern __shared__ __align__(128) char smdyn[];
    const uint32_t su = smem_u32(smdyn);

    const int tid  = threadIdx.x;
    const int lane = tid & 31;
    const int wid  = tid >> 5;
    const int wm   = (wid >> 2) * 64;
    const int wn   = (wid & 3) * (NT / 4);

    const int m0 = blockIdx.y * 128;
    const int n0 = blockIdx.x * NT;
    const int z  = blockIdx.z;

    const long aOff = (long)(z / hDiv) * sAo + (long)(z % hDiv) * sAi;
    const long bOff = (long)(z / hDiv) * sBo + (long)(z % hDiv) * sBi;
    const __half* AHb = AH + aOff;
    const __half* BHb = BH + bOff;
    const __half* BLb = TWOP ? (BL + bOff) : nullptr;
    const int mRem = M - m0;

    const int aRow  = (lane & 7) + ((lane >> 3) & 1) * 8;
    const int aSlab = (lane >> 4) * 16;

    float acc[4][NN][4];
#pragma unroll
    for (int i = 0; i < 4; i++)
#pragma unroll
        for (int j = 0; j < NN; j++)
#pragma unroll
            for (int r = 0; r < 4; r++) acc[i][j][r] = 0.f;

    const int kChunks = K >> 6;
    const int nChunks = nAcc * kChunks;

    auto issue = [&](int c) {
        const int hn = c / kChunks;
        const int k0 = (c % kChunks) << 6;
        const __half* pa  = AHb + (long)hn * accA;
        const __half* pb[2] = { BHb + (long)hn * accB,
                                TWOP ? (BLb + (long)hn * accB) : nullptr };
        const uint32_t buf = su + (uint32_t)(c % NST) * STAGE;
#pragma unroll
        for (int j = 0; j < NU; ++j) {
            const int u = tid + j * 256;
            const __half* src;
            uint32_t dst;
            int vsz;
            if (u < 1024) {
                const int row = u >> 3, g = u & 7;
                const int rr = (row < mRem) ? row : 0;
                vsz = (row < mRem) ? 16 : 0;
                src = pa + (long)(m0 + rr) * K + k0 + g * 8;
                dst = buf + (uint32_t)row * 128u + (uint32_t)((g ^ (row & 7)) << 4);
            } else {
                const int ub = u - 1024;
                const int pl = TWOP ? (ub / BPU) : 0;
                const int w  = TWOP ? (ub % BPU) : ub;
                const int row = w >> 3, g = w & 7;
                const int rr = (n0 + row < N) ? row : 0;
                vsz = (n0 + row < N) ? 16 : 0;
                src = pb[pl] + (long)(n0 + rr) * K + k0 + g * 8;
                dst = buf + 16384u + (uint32_t)pl * (uint32_t)(NT * 128)
                          + (uint32_t)row * 128u + (uint32_t)((g ^ (row & 7)) << 4);
            }
            CP16(dst, src, vsz);
        }
    };

    issue(0); CP_COMMIT;
    if (nChunks > 1) { issue(1); CP_COMMIT; }

    for (int c = 0; c < nChunks; ++c) {
        if (c + 1 < nChunks) { CP_WAIT1; } else { CP_WAIT0; }
        __syncthreads();
        if (NST == 3 && c + 2 < nChunks) { issue(c + 2); CP_COMMIT; }

        const uint32_t buf = su + (uint32_t)(c % NST) * STAGE;
        const uint32_t aHi = buf;
        const uint32_t bHi = buf + 16384;
        const uint32_t bLo = buf + 16384 + NT * 128;

#pragma unroll
        for (int ks = 0; ks < 4; ++ks) {
            const int cbase = ks * 32;
            uint32_t ah[4][4];
#pragma unroll
            for (int mt = 0; mt < 4; ++mt) {
                const int row = wm + mt * 16 + aRow;
                const int cb  = cbase + aSlab;
                const uint32_t off = (uint32_t)row * 128u
                                   + (uint32_t)((((cb >> 4) ^ (row & 7))) << 4);
                LDMX4(ah[mt], aHi + off);
            }
            uint32_t bh[NN][2], bl[NN][2];
#pragma unroll
            for (int p = 0; p < NN / 2; ++p) {
                const int mr  = lane >> 3;
                const int row = wn + p * 16 + (mr >> 1) * 8 + (lane & 7);
                const int cb  = cbase + (mr & 1) * 16;
                const uint32_t off = (uint32_t)row * 128u
                                   + (uint32_t)((((cb >> 4) ^ (row & 7))) << 4);
                uint32_t q[4];
                LDMX4(q, bHi + off);
                bh[2*p][0] = q[0]; bh[2*p][1] = q[1];
                bh[2*p+1][0] = q[2]; bh[2*p+1][1] = q[3];
                if (TWOP) {
                    LDMX4(q, bLo + off);
                    bl[2*p][0] = q[0]; bl[2*p][1] = q[1];
                    bl[2*p+1][0] = q[2]; bl[2*p+1][1] = q[3];
                }
            }
#pragma unroll
            for (int mt = 0; mt < 4; ++mt)
#pragma unroll
                for (int nt = 0; nt < NN; ++nt)
                    MMA16816(acc[mt][nt], ah[mt], bh[nt]);
            if (TWOP) {
#pragma unroll
                for (int mt = 0; mt < 4; ++mt)
#pragma unroll
                    for (int nt = 0; nt < NN; ++nt)
                        MMA16816(acc[mt][nt], ah[mt], bl[nt]);
            }
        }

        if (NST == 2) {
            __syncthreads();
            if (c + 2 < nChunks) { issue(c + 2); CP_COMMIT; }
        }
    }

    // ---- epilogue ----
    float*  Cfp = (OMODE == 0) ? (Cf + (long)z * sC) : nullptr;
    __half* CHp = (OMODE == 1) ? (CH + (long)z * sC) : nullptr;

#pragma unroll
    for (int mt = 0; mt < 4; ++mt) {
#pragma unroll
        for (int nt = 0; nt < NN; ++nt) {
            const int m1 = m0 + wm + mt * 16 + (lane >> 2);
            const int n  = n0 + wn + nt * 8 + (lane & 3) * 2;
            if (n >= N) continue;
#pragma unroll
            for (int half = 0; half < 2; ++half) {
                const int m = m1 + half * 8;
                if (m >= M) continue;
                const float x = acc[mt][nt][half * 2 + 0] * scale;
                const float y = acc[mt][nt][half * 2 + 1] * scale;
                if (OMODE == 1) {
                    __half2 h2 = __floats2half2_rn(x, y);
                    *reinterpret_cast<uint32_t*>(CHp + (long)m * N + n) =
                        *reinterpret_cast<uint32_t*>(&h2);
                } else {
                    *reinterpret_cast<float2*>(Cfp + (long)m * N + n) = make_float2(x, y);
                }
            }
        }
    }
}

// ---------------------------------------------------------------------------
// Two-phase instance-norm stats + softmax (emits hi-only probs)
// ---------------------------------------------------------------------------
__inline__ __device__ float warpSum(float v) {
#pragma unroll
    for (int o = 16; o; o >>= 1) v += __shfl_xor_sync(0xffffffffu, v, o);
    return v;
}
__inline__ __device__ float warpMax(float v) {
#pragma unroll
    for (int o = 16; o; o >>= 1) v = fmaxf(v, __shfl_xor_sync(0xffffffffu, v, o));
    return v;
}

__global__ void stats_p1(const float* __restrict__ S, float2* __restrict__ part, int C)
{
    const int z = blockIdx.x, p = blockIdx.y;
    const long n = (long)C * KV;
    const long len = (n + 15) >> 4;
    const long lo = (long)p * len;
    const long hi = (lo + len < n) ? lo + len : n;
    const float* base = S + (long)z * n;
    float s = 0.f, sq = 0.f;
    for (long i = lo + threadIdx.x; i < hi; i += blockDim.x) {
        const float x = base[i];
        s += x; sq += x * x;
    }
    __shared__ float sh1[8], sh2[8];
    s = warpSum(s); sq = warpSum(sq);
    const int w = threadIdx.x >> 5, l = threadIdx.x & 31;
    if (l == 0) { sh1[w] = s; sh2[w] = sq; }
    __syncthreads();
    if (threadIdx.x == 0) {
        float ts = 0.f, tq = 0.f;
#pragma unroll
        for (int i = 0; i < 8; i++) { ts += sh1[i]; tq += sh2[i]; }
        part[z * 16 + p] = make_float2(ts, tq);
    }
}

__global__ void stats_p2(const float2* __restrict__ part, float* __restrict__ stats, int C)
{
    const int z = blockIdx.x;
    const int l = threadIdx.x;
    float s = 0.f, sq = 0.f;
    if (l < 16) { const float2 v = part[z * 16 + l]; s = v.x; sq = v.y; }
    s = warpSum(s); sq = warpSum(sq);
    if (l == 0) {
        const float invn = 1.f / (float)((long)C * KV);
        const float mean = s * invn;
        const float var  = sq * invn - mean * mean;
        stats[z * 2 + 0] = mean;
        stats[z * 2 + 1] = rsqrtf(var + 1e-5f);
    }
}

__global__ void softmax_kernel(const float* __restrict__ S,
                               __half* __restrict__ PH,
                               const float* __restrict__ stats, int C)
{
    const int row = blockIdx.x;
    const int z = row / C;
    const float inv = stats[z * 2 + 1];
    const float* p = S + (long)row * KV;
    __half* ph = PH + (long)row * KV;
    const int tid = threadIdx.x;
    const int w = tid >> 5, l = tid & 31;

    __shared__ float sred[8];
    __shared__ float s_mx, s_se;
    __shared__ float se_buf[960];

    float mx = -1e30f;
    for (int i = tid; i < KV; i += 256) mx = fmaxf(mx, p[i]);
    mx = warpMax(mx);
    if (l == 0) sred[w] = mx;
    __syncthreads();
    if (tid == 0) {
        float m = sred[0];
#pragma unroll
        for (int i = 1; i < 8; i++) m = fmaxf(m, sred[i]);
        s_mx = m;
    }
    __syncthreads();
    mx = s_mx;

    float se = 0.f;
    for (int i = tid; i < KV; i += 256) {
        const float e = expf((p[i] - mx) * inv);
        se_buf[i] = e;
        se += e;
    }
    se = warpSum(se);
    __syncthreads();
    if (l == 0) sred[w] = se;
    __syncthreads();
    if (tid == 0) {
        float t = 0.f;
#pragma unroll
        for (int i = 0; i < 8; i++) t += sred[i];
        s_se = 1.f / t;
    }
    __syncthreads();
    const float r = s_se;
    for (int i = tid; i < KV; i += 256)
        ph[i] = __float2half_rn(se_buf[i] * r);
}

// ---------------------------------------------------------------------------
// Host launch
// ---------------------------------------------------------------------------
struct HTensors { const __half *h, *l; };

template<int NT, bool TWOP, int OMODE>
static inline void rungemm(dim3 grid, cudaStream_t st,
                           const __half* AH, const __half* BH, const __half* BL,
                           float* Cf, __half* CH,
                           int M, int N, int K,
                           long sAo, long sAi, long sBo, long sBi, long sC,
                           int hDiv, int nAcc, long accA, long accB, float scale)
{
    constexpr int NPL   = TWOP ? 2 : 1;
    constexpr int STAGE = 16384 + NPL * NT * 128;
    constexpr int NST   = (TWOP && NT >= 256) ? 2 : 3;
    constexpr int DSM   = NST * STAGE;
    cudaFuncSetAttribute(gemm_hf<NT, TWOP, OMODE>,
                         cudaFuncAttributeMaxDynamicSharedMemorySize, DSM);
    gemm_hf<NT, TWOP, OMODE><<<grid, 256, DSM, st>>>(
        AH, BH, BL, Cf, CH, M, N, K, sAo, sAi, sBo, sBi, sC,
        hDiv, nAcc, accA, accB, scale);
}

// R13-proven stream topology: serial Kt,V on origin; fork after V; 3 created
// streams; 3 joins; branch 0 on origin.
struct StreamPack {
    cudaStream_t st[3];
    cudaEvent_t fork, join[3];
    StreamPack() {
        for (int i = 0; i < 3; ++i) {
            cudaStreamCreateWithFlags(&st[i], cudaStreamNonBlocking);
            cudaEventCreateWithFlags(&join[i], cudaEventDisableTiming);
        }
        cudaEventCreateWithFlags(&fork, cudaEventDisableTiming);
    }
};
static StreamPack& sp() { static StreamPack s; return s; }

extern "C" void kernel_launch(void* const* d_in, const int* in_sizes, int n_in,
                              void* d_out, int out_size)
{
    (void)n_in; (void)out_size;

    // ---- input-order detection (dict order has Wq/Wo interleaved) ----
    int ie[4], ieall, iwq[4], iwo[4], iwk, iwv;
    const int SZ_WK   = 4 * 960 * 960;
    const int SZ_EMB1 = 8 * 1024 * 64;
    const int SZ_WO1  = 64 * 64;

    if (in_sizes[0] == SZ_WK) {
        iwk = 0;
        iwo[0] = 1; iwo[1] = 2; iwo[2] = 3; iwo[3] = 4;
        iwq[0] = 5; iwq[1] = 6; iwq[2] = 7; iwq[3] = 8;
        iwv = 9;
        ie[0] = 10; ie[1] = 11; ie[2] = 12; ie[3] = 13;
        ieall = 14;
    } else if (in_sizes[0] == SZ_EMB1 && in_sizes[5] == SZ_WK) {
        ie[0] = 0; ie[1] = 1; ie[2] = 2; ie[3] = 3; ieall = 4;
        iwk = 5;
        iwo[0] = 6; iwo[1] = 7; iwo[2] = 8; iwo[3] = 9;
        iwq[0] = 10; iwq[1] = 11; iwq[2] = 12; iwq[3] = 13;
        iwv = 14;
    } else if (in_sizes[6] == SZ_WO1) {
        ie[0] = 0; ie[1] = 1; ie[2] = 2; ie[3] = 3; ieall = 4;
        iwq[0] = 5;  iwo[0] = 6;
        iwq[1] = 7;  iwo[1] = 8;
        iwq[2] = 9;  iwo[2] = 10;
        iwq[3] = 11; iwo[3] = 12;
        iwk = 13; iwv = 14;
    } else {
        ie[0] = 0; ie[1] = 1; ie[2] = 2; ie[3] = 3; ieall = 4;
        iwq[0] = 5; iwq[1] = 6; iwq[2] = 7; iwq[3] = 8;
        iwo[0] = 9; iwo[1] = 10; iwo[2] = 11; iwo[3] = 12;
        iwk = 13; iwv = 14;
    }

    float* out = (float*)d_out;

    __half *inH, *inL;
    __half *ktH, *vH, *qtH, *pHg, *cHg;
    float *pS, *pSt;
    float2 *pPart;
    cudaGetSymbolAddress((void**)&inH, g_inH);
    cudaGetSymbolAddress((void**)&inL, g_inL);
    cudaGetSymbolAddress((void**)&ktH, g_KtH);
    cudaGetSymbolAddress((void**)&vH,  g_VH);
    cudaGetSymbolAddress((void**)&qtH, g_QtH);
    cudaGetSymbolAddress((void**)&pHg, g_PH);
    cudaGetSymbolAddress((void**)&cHg, g_cH);
    cudaGetSymbolAddress((void**)&pS,  g_S);
    cudaGetSymbolAddress((void**)&pSt, g_stats);
    cudaGetSymbolAddress((void**)&pPart, g_part);

    const int Cs[4]   = {64, 128, 256, 512};
    const int cumC[4] = {0, 64, 192, 448};

    // ---- single fused conversion over the whole arena (origin stream) ----
    size_t off[15]; int idx[15]; size_t cur = 0; int t = 0;
    for (int i = 0; i < 4; ++i) { idx[t] = ie[i];  off[t] = cur; cur += (size_t)Bb * Nn * Cs[i]; ++t; }
    idx[t] = ieall; off[t] = cur; cur += (size_t)Bb * Nn * KV; ++t;
    for (int i = 0; i < 4; ++i) { idx[t] = iwq[i]; off[t] = cur; cur += (size_t)Hh * Cs[i] * Cs[i]; ++t; }
    idx[t] = iwk; off[t] = cur; cur += (size_t)Hh * KV * KV; ++t;
    idx[t] = iwv; off[t] = cur; cur += (size_t)Hh * KV * KV; ++t;
    for (int i = 0; i < 4; ++i) { idx[t] = iwo[i]; off[t] = cur; cur += (size_t)Cs[i] * Cs[i]; ++t; }

    ConvParams P;
    for (int j = 0; j < 15; ++j) {
        P.src[j]  = (const float*)d_in[idx[j]];
        P.cum4[j] = (long)(off[j] / 4);
    }
    P.cum4[15] = (long)(cur / 4);
    const long total4 = (long)(cur / 4);
    conv_all<<<(unsigned)((total4 + 255) / 256), 256>>>(P, inH, inL, total4);

    HTensors embT[4], embAllT, WqT[4], WkT, WvT, WoT[4];
    for (int i = 0; i < 4; ++i) embT[i] = { inH + off[i], inL + off[i] };
    embAllT = { inH + off[4], inL + off[4] };
    for (int i = 0; i < 4; ++i) WqT[i] = { inH + off[5 + i], inL + off[5 + i] };
    WkT = { inH + off[9],  inL + off[9]  };
    WvT = { inH + off[10], inL + off[10] };
    for (int i = 0; i < 4; ++i) WoT[i] = { inH + off[11 + i], inL + off[11 + i] };

    const float sscale = 0.032274861f;  // 1/sqrt(960)

    // 1) Kt: single-product (Wk_hi x emb_hi), half-hi out
    rungemm<256, false, 1>(dim3(4, 8, Bb * Hh), 0,
        WkT.h, embAllT.h, nullptr, nullptr, ktH,
        KV, Nn, KV,
        0, (long)KV * KV, (long)Nn * KV, 0, (long)KV * Nn,
        Hh, 1, 0, 0, 1.f);

    // 2) V: single-product (emb_hi x Wv_hi), half-hi out
    rungemm<256, false, 1>(dim3(4, 8, Bb * Hh), 0,
        embAllT.h, WvT.h, nullptr, nullptr, vH,
        Nn, KV, KV,
        (long)Nn * KV, 0, 0, (long)KV * KV, (long)Nn * KV,
        Hh, 1, 0, 0, 1.f);

    // ---- fork after V: branches 1..3 on created streams, branch 0 on origin ----
    StreamPack& S = sp();
    cudaEventRecord(S.fork, 0);
    for (int i = 0; i < 3; ++i) cudaStreamWaitEvent(S.st[i], S.fork, 0);

    long outOff[4];
    {
        long o = 0;
        for (int i = 0; i < 4; ++i) { outOff[i] = o; o += (long)Bb * Nn * Cs[i]; }
    }

    for (int i = 0; i < 4; ++i) {
        const int C = Cs[i];
        const int mtC = (C + 127) / 128;
        cudaStream_t st = (i == 0) ? (cudaStream_t)0 : S.st[i - 1];

        __half* qtHb = qtH + (size_t)cumC[i] * 32 * 1024;
        float*  pSb  = pS  + (size_t)cumC[i] * 32 * 960;
        __half* pHb  = pHg + (size_t)cumC[i] * 32 * 960;
        __half* cHb  = cHg + (size_t)cumC[i] * 8 * 1024;
        float*  stB  = pSt + (size_t)i * 64;
        float2* ptB  = pPart + (size_t)i * 512;

        // 3) Qt: 2-product (Wq_hi x (emb_hi+emb_lo)), half-hi out
        rungemm<256, true, 1>(dim3(4, mtC, Bb * Hh), st,
            WqT[i].h, embT[i].h, embT[i].l, nullptr, qtHb,
            C, Nn, C,
            0, (long)C * C, (long)Nn * C, 0, (long)C * Nn,
            Hh, 1, 0, 0, 1.f);

        // 4) S: single-product (Qt_hi x Kt_hi), fp32 out
        rungemm<256, false, 0>(dim3(4, mtC, Bb * Hh), st,
            qtHb, ktH, nullptr, pSb, nullptr,
            C, KV, Nn,
            (long)C * Nn, 0, (long)KV * Nn, 0, (long)C * KV,
            1, 1, 0, 0, sscale);

        // stats (two-phase)
        stats_p1<<<dim3(Bb * Hh, 16), 256, 0, st>>>(pSb, ptB, C);
        stats_p2<<<Bb * Hh, 32, 0, st>>>(ptB, stB, C);

        // softmax -> hi-only probs
        softmax_kernel<<<Bb * Hh * C, 256, 0, st>>>(pSb, pHb, stB, C);

        // 5) ctx: single-product (V_hi x P_hi), half-hi out
        if (C >= 256) {
            rungemm<256, false, 1>(dim3((C + 255) / 256, 8, Bb), st,
                vH, pHb, nullptr, nullptr, cHb,
                Nn, C, KV,
                (long)Hh * Nn * KV, 0, (long)Hh * C * KV, 0, (long)Nn * C,
                1, Hh, (long)Nn * KV, (long)C * KV, 0.25f);
        } else if (C == 128) {
            rungemm<128, false, 1>(dim3(1, 8, Bb), st,
                vH, pHb, nullptr, nullptr, cHb,
                Nn, C, KV,
                (long)Hh * Nn * KV, 0, (long)Hh * C * KV, 0, (long)Nn * C,
                1, Hh, (long)Nn * KV, (long)C * KV, 0.25f);
        } else {
            rungemm<64, false, 1>(dim3(1, 8, Bb), st,
                vH, pHb, nullptr, nullptr, cHb,
                Nn, C, KV,
                (long)Hh * Nn * KV, 0, (long)Hh * C * KV, 0, (long)Nn * C,
                1, Hh, (long)Nn * KV, (long)C * KV, 0.25f);
        }

        // 6) out: 2-product (ctx_hi x (Wo_hi+Wo_lo)), fp32 out
        if (C >= 256) {
            rungemm<256, true, 0>(dim3((C + 255) / 256, 8, Bb), st,
                cHb, WoT[i].h, WoT[i].l, out + outOff[i], nullptr,
                Nn, C, C,
                (long)Nn * C, 0, 0, 0, (long)Nn * C,
                1, 1, 0, 0, 1.f);
        } else if (C == 128) {
            rungemm<128, true, 0>(dim3(1, 8, Bb), st,
                cHb, WoT[i].h, WoT[i].l, out + outOff[i], nullptr,
                Nn, C, C,
                (long)Nn * C, 0, 0, 0, (long)Nn * C,
                1, 1, 0, 0, 1.f);
        } else {
            rungemm<64, true, 0>(dim3(1, 8, Bb), st,
                cHb, WoT[i].h, WoT[i].l, out + outOff[i], nullptr,
                Nn, C, C,
                (long)Nn * C, 0, 0, 0, (long)Nn * C,
                1, 1, 0, 0, 1.f);
        }
    }

    // ---- join back to origin stream ----
    for (int i = 0; i < 3; ++i) {
        cudaEventRecord(S.join[i], S.st[i]);
        cudaStreamWaitEvent(0, S.join[i], 0);
    }
}